// round 14
// baseline (speedup 1.0000x reference)
#include <cuda_runtime.h>
#include <cuda_fp16.h>
#include <cstdint>

// Problem shape (fixed)
#define BB 8
#define NN 256
#define DD 128
#define KK 256   // 2*D

// Scratch (half: mantissa == tf32, range safe for O(1) data)
__device__ __half g_Pih[BB * NN * KK];   // Pi with b1 folded in
__device__ __half g_Pjh[BB * NN * KK];
__device__ __half g_W2h[DD * KK];        // W2 transposed to [c][k]

// ---------------------------------------------------------------------------
// Helpers
// ---------------------------------------------------------------------------
__device__ __forceinline__ uint32_t h2_as_u32(__half2 h) {
    union { __half2 h; uint32_t u; } cvt;
    cvt.h = h;
    return cvt.u;
}
__device__ __forceinline__ __half2 u32_as_h2(uint32_t u) {
    union { uint32_t u; __half2 h; } cvt;
    cvt.u = u;
    return cvt.h;
}

// fp16 MMA m16n8k16, fp32 accumulate
__device__ __forceinline__ void mma_f16(float* d,
                                        uint32_t a0, uint32_t a1, uint32_t a2, uint32_t a3,
                                        uint32_t b0, uint32_t b1) {
    asm volatile(
        "mma.sync.aligned.m16n8k16.row.col.f32.f16.f16.f32 "
        "{%0,%1,%2,%3}, {%4,%5,%6,%7}, {%8,%9}, {%0,%1,%2,%3};"
        : "+f"(d[0]), "+f"(d[1]), "+f"(d[2]), "+f"(d[3])
        : "r"(a0), "r"(a1), "r"(a2), "r"(a3), "r"(b0), "r"(b1));
}

// ldmatrix 4x m8n8 b16 tiles
__device__ __forceinline__ void ldx4(uint32_t* r, uint32_t addr) {
    asm volatile(
        "ldmatrix.sync.aligned.m8n8.x4.shared.b16 {%0,%1,%2,%3}, [%4];"
        : "=r"(r[0]), "=r"(r[1]), "=r"(r[2]), "=r"(r[3]) : "r"(addr));
}

// ---------------------------------------------------------------------------
// Tour output
// ---------------------------------------------------------------------------
__global__ void tour_kernel(float* __restrict__ out) {
    int idx = blockIdx.x * 256 + threadIdx.x;
    if (idx < BB * NN) out[idx] = (float)(idx & (NN - 1));
}

// ---------------------------------------------------------------------------
// Projection kernel (fp32 math, half output).
// 16 n-rows per block -> 128 blocks: halves W1 L2 traffic vs 8-row blocks.
// ---------------------------------------------------------------------------
#define PRJ 16

__global__ __launch_bounds__(256) void proj_kernel(const float* __restrict__ x,
                                                   const float* __restrict__ W1,
                                                   const float* __restrict__ b1) {
    int blk = blockIdx.x;              // 0..127
    int b   = blk >> 4;
    int n0  = (blk & 15) * PRJ;

    __shared__ float xs[PRJ + 1][DD];
    for (int t = threadIdx.x; t < (PRJ + 1) * DD; t += 256) {
        int r = t / DD, d = t % DD;
        int n = (n0 + r) & (NN - 1);
        xs[r][d] = x[((size_t)b * NN + n) * DD + d];
    }
    __syncthreads();

    int c = threadIdx.x;
    float accPi[PRJ], accPj[PRJ];
#pragma unroll
    for (int r = 0; r < PRJ; r++) { accPi[r] = 0.f; accPj[r] = 0.f; }

#pragma unroll 2
    for (int d = 0; d < DD; d++) {
        float wa = W1[(0 * DD + d) * KK + c];
        float wb = W1[(1 * DD + d) * KK + c];
        float wc = W1[(2 * DD + d) * KK + c];
        float wd = W1[(3 * DD + d) * KK + c];
#pragma unroll
        for (int r = 0; r < PRJ; r++) {
            float xv  = xs[r][d];
            float xnv = xs[r + 1][d];
            accPi[r] += xv * wa + xnv * wb;
            accPj[r] += xv * wc + xnv * wd;
        }
    }
    float b1c = b1[c];
#pragma unroll
    for (int r = 0; r < PRJ; r++) {
        int n = n0 + r;
        size_t off = ((size_t)b * NN + n) * KK + c;
        g_Pih[off] = __float2half_rn(accPi[r] + b1c);
        g_Pjh[off] = __float2half_rn(accPj[r]);
    }
}

// ---------------------------------------------------------------------------
// W2 prep: transpose [k][c] fp32 -> [c][k] half
// ---------------------------------------------------------------------------
__global__ void w2prep_kernel(const float* __restrict__ W2) {
    int idx = blockIdx.x * 256 + threadIdx.x;  // k*128 + c
    int k = idx >> 7, c = idx & 127;
    g_W2h[c * KK + k] = __float2half_rn(W2[idx]);
}

// ---------------------------------------------------------------------------
// Pair kernel: CTA = (b, {i0,i0+1}, j-tile of 128), fp16 m16n8k16.
// 512 thr = 16 warps = 8(wy: j 16-range) x 2(wx: c 64-range).
// Each warp handles BOTH i's on ONE 16-row j block -> whole-warp mask skip:
// a fully masked warp issues nothing (no B loads either).
// All chunk loads issue up front (independent), then math + MMAs.
// ---------------------------------------------------------------------------
#define BROW 264                       // half stride: 256+8 (conflict-free)

// byte offsets in dynamic smem
#define OFF_BH   0                     // 128*264*2 = 67584
#define OFF_PJ   67584                 // 128*264*2 = 67584
#define OFF_PI   135168                // 512*2     = 1024
#define OFF_B2   136192                // 512
#define OFF_W3   136704                // 512
#define OFF_RED  137216                // 2*128*2*4 = 2048
#define SMEM_BYTES 139264

__global__ __launch_bounds__(512, 1) void pair_kernel(const float* __restrict__ b2g,
                                                      const float* __restrict__ w3g,
                                                      const float* __restrict__ b3g,
                                                      float* __restrict__ outm) {
    extern __shared__ char smem[];
    __half* Bh  = (__half*)(smem + OFF_BH);
    __half* Pjs = (__half*)(smem + OFF_PJ);
    __half* Pis = (__half*)(smem + OFF_PI);
    float*  b2s = (float*)(smem + OFF_B2);
    float*  w3s = (float*)(smem + OFF_W3);
    float*  red = (float*)(smem + OFF_RED);

    int tid  = threadIdx.x;
    int lane = tid & 31, wid = tid >> 5;
    int wx = wid & 1;                  // c 64-range
    int wy = wid >> 1;                 // j 16-range (0..7)
    int g  = lane >> 2, tg = lane & 3;

    int bid = blockIdx.x;
    int jt = bid & 1;
    int ig = (bid >> 1) & 127;
    int b  = bid >> 8;
    int j0 = jt << 7, i0 = ig << 1;
    if (i0 > j0 + 125) return;         // fully masked tile (output zeroed by memset)

    int jb = j0 + wy * 16;             // this warp's j block base
    bool okA = (jb + 15) >= i0 + 2;    // block valid for i0   (okB implies okA)
    bool okB = (jb + 15) >= i0 + 3;    // block valid for i0+1

    // Prologue: W2 image, Pj j-tile, Pi rows, b2, W3
    {
        const uint4* wsrc = (const uint4*)g_W2h;
#pragma unroll
        for (int q = tid; q < 4096; q += 512) {
            int cc = q >> 5, qq = q & 31;
            *(uint4*)&Bh[cc * BROW + qq * 8] = wsrc[cc * 32 + qq];
        }
        const uint4* psrc = (const uint4*)&g_Pjh[(size_t)(b * NN + j0) * KK];
#pragma unroll
        for (int q = tid; q < 4096; q += 512) {
            int jj = q >> 5, qq = q & 31;
            *(uint4*)&Pjs[jj * BROW + qq * 8] = psrc[jj * 32 + qq];
        }
        const __half* pisrc = &g_Pih[(size_t)(b * NN + i0) * KK];
        Pis[tid] = pisrc[tid];          // 512 halves = both i rows
        if (tid < 128) { b2s[tid] = b2g[tid]; w3s[tid] = w3g[tid]; }
    }
    __syncthreads();   // the only barrier before the epilogue

    float acc[2][8][4];
#pragma unroll
    for (int i = 0; i < 2; i++)
#pragma unroll
        for (int n = 0; n < 8; n++)
#pragma unroll
            for (int q = 0; q < 4; q++) acc[i][n][q] = 0.f;

    if (okA) {
        // ldmatrix lane addresses (bytes)
        uint32_t BhAddr = (uint32_t)__cvta_generic_to_shared(Bh);
        uint32_t PjAddr = (uint32_t)__cvta_generic_to_shared(Pjs);
        int rowL = lane & 15, kL = (lane >> 4) * 8;
        uint32_t bAddr[4];
#pragma unroll
        for (int t = 0; t < 4; t++)
            bAddr[t] = (uint32_t)((wx * 64 + t * 16 + rowL) * BROW + kL) * 2 + BhAddr;
        uint32_t pjAddr = (uint32_t)((wy * 16 + rowL) * BROW + kL) * 2 + PjAddr;

        const __half2 zero2 = __float2half2_rn(0.f);
        const __half* Pi0 = &Pis[0];
        const __half* Pi1 = &Pis[256];

#pragma unroll 4
        for (int c = 0; c < 16; c++) {
            int k0 = c << 4;

            // All loads up front, fully independent
            uint32_t bq[4][4];
#pragma unroll
            for (int t = 0; t < 4; t++) ldx4(bq[t], bAddr[t] + (uint32_t)k0 * 2);
            uint32_t pq[4];
            ldx4(pq, pjAddr + (uint32_t)k0 * 2);
            __half2 pil0 = *(const __half2*)&Pi0[k0 + 2 * tg];
            __half2 pih0 = *(const __half2*)&Pi0[k0 + 2 * tg + 8];
            __half2 pil1 = *(const __half2*)&Pi1[k0 + 2 * tg];
            __half2 pih1 = *(const __half2*)&Pi1[k0 + 2 * tg + 8];

            // i = i0
            {
                uint32_t a0 = h2_as_u32(__hmax2(__hadd2(u32_as_h2(pq[0]), pil0), zero2));
                uint32_t a1 = h2_as_u32(__hmax2(__hadd2(u32_as_h2(pq[1]), pil0), zero2));
                uint32_t a2 = h2_as_u32(__hmax2(__hadd2(u32_as_h2(pq[2]), pih0), zero2));
                uint32_t a3 = h2_as_u32(__hmax2(__hadd2(u32_as_h2(pq[3]), pih0), zero2));
#pragma unroll
                for (int t = 0; t < 4; t++) {
                    mma_f16(acc[0][2 * t],     a0, a1, a2, a3, bq[t][0], bq[t][2]);
                    mma_f16(acc[0][2 * t + 1], a0, a1, a2, a3, bq[t][1], bq[t][3]);
                }
            }
            // i = i0 + 1
            if (okB) {
                uint32_t a0 = h2_as_u32(__hmax2(__hadd2(u32_as_h2(pq[0]), pil1), zero2));
                uint32_t a1 = h2_as_u32(__hmax2(__hadd2(u32_as_h2(pq[1]), pil1), zero2));
                uint32_t a2 = h2_as_u32(__hmax2(__hadd2(u32_as_h2(pq[2]), pih1), zero2));
                uint32_t a3 = h2_as_u32(__hmax2(__hadd2(u32_as_h2(pq[3]), pih1), zero2));
#pragma unroll
                for (int t = 0; t < 4; t++) {
                    mma_f16(acc[1][2 * t],     a0, a1, a2, a3, bq[t][0], bq[t][2]);
                    mma_f16(acc[1][2 * t + 1], a0, a1, a2, a3, bq[t][1], bq[t][3]);
                }
            }
        }
    }

    // Epilogue: relu(C+b2).W3 partial dots, shfl reduce over tg, smem over wx
    float b3v = b3g[0];
#pragma unroll
    for (int i = 0; i < 2; i++) {
        float s0 = 0.f, s1 = 0.f;
#pragma unroll
        for (int n = 0; n < 8; n++) {
            int c0 = wx * 64 + n * 8 + tg * 2;
            float bA  = b2s[c0],     wA  = w3s[c0];
            float bBv = b2s[c0 + 1], wBv = w3s[c0 + 1];
            s0 += fmaxf(acc[i][n][0] + bA, 0.f) * wA
                + fmaxf(acc[i][n][1] + bBv, 0.f) * wBv;
            s1 += fmaxf(acc[i][n][2] + bA, 0.f) * wA
                + fmaxf(acc[i][n][3] + bBv, 0.f) * wBv;
        }
        s0 += __shfl_xor_sync(0xffffffffu, s0, 1);
        s0 += __shfl_xor_sync(0xffffffffu, s0, 2);
        s1 += __shfl_xor_sync(0xffffffffu, s1, 1);
        s1 += __shfl_xor_sync(0xffffffffu, s1, 2);
        if (tg == 0) {
            int r0 = wy * 16 + g;
            red[(i * 128 + r0) * 2 + wx]     = s0;
            red[(i * 128 + r0 + 8) * 2 + wx] = s1;
        }
    }
    __syncthreads();

    if (tid < 256) {
        int i  = tid >> 7;
        int jj = tid & 127;
        const float* rp = &red[(i * 128 + jj) * 2];
        float sum = rp[0] + rp[1] + b3v;
        int iG = i0 + i, j = j0 + jj;
        bool valid = (j >= iG + 2) && ((j - iG) != (NN - 1));
        outm[((size_t)(b * NN + iG)) * NN + j] = valid ? tanhf(sum) : 0.f;
    }
}

// ---------------------------------------------------------------------------
// Launcher
// ---------------------------------------------------------------------------
extern "C" void kernel_launch(void* const* d_in, const int* in_sizes, int n_in,
                              void* d_out, int out_size) {
    const float* x  = (const float*)d_in[0];
    const float* W1 = (const float*)d_in[1];
    const float* b1 = (const float*)d_in[2];
    const float* W2 = (const float*)d_in[3];
    const float* b2 = (const float*)d_in[4];
    const float* W3 = (const float*)d_in[5];
    const float* b3 = (const float*)d_in[6];
    float* out = (float*)d_out;

    const int MAT  = BB * NN * NN;   // 524288
    const int TOUR = BB * NN;        // 2048

    size_t matOff = 0;
    bool hasTour = false;
    if (out_size >= MAT + TOUR) { hasTour = true; matOff = (size_t)out_size - MAT; }

    cudaFuncSetAttribute(pair_kernel, cudaFuncAttributeMaxDynamicSharedMemorySize,
                         SMEM_BYTES);

    cudaMemsetAsync(d_out, 0, (size_t)out_size * sizeof(float), 0);
    if (hasTour) tour_kernel<<<(TOUR + 255) / 256, 256>>>(out);

    proj_kernel<<<128, 256>>>(x, W1, b1);
    w2prep_kernel<<<128, 256>>>(W2);
    pair_kernel<<<BB * 128 * 2, 512, SMEM_BYTES>>>(b2, W3, b3, out + matOff);
}

// round 16
// speedup vs baseline: 1.1017x; 1.1017x over previous
#include <cuda_runtime.h>
#include <cuda_fp16.h>
#include <cstdint>

// Problem shape (fixed)
#define BB 8
#define NN 256
#define DD 128
#define KK 256   // 2*D

// Scratch (half: mantissa == tf32, range safe for O(1) data)
__device__ __half g_Pih[BB * NN * KK];   // Pi with b1 folded in
__device__ __half g_Pjh[BB * NN * KK];
__device__ __half g_W2h[DD * KK];        // W2 transposed to [c][k]

// ---------------------------------------------------------------------------
// Helpers
// ---------------------------------------------------------------------------
__device__ __forceinline__ uint32_t h2_as_u32(__half2 h) {
    union { __half2 h; uint32_t u; } cvt;
    cvt.h = h;
    return cvt.u;
}
__device__ __forceinline__ __half2 u32_as_h2(uint32_t u) {
    union { uint32_t u; __half2 h; } cvt;
    cvt.u = u;
    return cvt.h;
}

// f32x2 packed helpers (full-rate fp32 FMA path on sm_103a)
__device__ __forceinline__ unsigned long long pack2(float x, float y) {
    unsigned long long r;
    asm("mov.b64 %0, {%1, %2};" : "=l"(r) : "f"(x), "f"(y));
    return r;
}
__device__ __forceinline__ void unpack2(unsigned long long v, float& x, float& y) {
    asm("mov.b64 {%0, %1}, %2;" : "=f"(x), "=f"(y) : "l"(v));
}
__device__ __forceinline__ unsigned long long fma2(unsigned long long a,
                                                   unsigned long long b,
                                                   unsigned long long c) {
    unsigned long long d;
    asm("fma.rn.f32x2 %0, %1, %2, %3;" : "=l"(d) : "l"(a), "l"(b), "l"(c));
    return d;
}

// fp16 MMA m16n8k16, fp32 accumulate
__device__ __forceinline__ void mma_f16(float* d,
                                        uint32_t a0, uint32_t a1, uint32_t a2, uint32_t a3,
                                        uint32_t b0, uint32_t b1) {
    asm volatile(
        "mma.sync.aligned.m16n8k16.row.col.f32.f16.f16.f32 "
        "{%0,%1,%2,%3}, {%4,%5,%6,%7}, {%8,%9}, {%0,%1,%2,%3};"
        : "+f"(d[0]), "+f"(d[1]), "+f"(d[2]), "+f"(d[3])
        : "r"(a0), "r"(a1), "r"(a2), "r"(a3), "r"(b0), "r"(b1));
}

// ldmatrix 4x m8n8 b16 tiles
__device__ __forceinline__ void ldx4(uint32_t* r, uint32_t addr) {
    asm volatile(
        "ldmatrix.sync.aligned.m8n8.x4.shared.b16 {%0,%1,%2,%3}, [%4];"
        : "=r"(r[0]), "=r"(r[1]), "=r"(r[2]), "=r"(r[3]) : "r"(addr));
}

// ---------------------------------------------------------------------------
// Projection kernel (fp32-exact math via packed f32x2 FMA, half output).
// 8 rows per block, 256 blocks. Row pairs share weights -> fma2 does 2 FMAs.
// ---------------------------------------------------------------------------
__global__ __launch_bounds__(256) void proj_kernel(const float* __restrict__ x,
                                                   const float* __restrict__ W1,
                                                   const float* __restrict__ b1) {
    int blk = blockIdx.x;              // 0..255
    int b   = blk >> 5;
    int n0  = (blk & 31) * 8;

    __shared__ float xs[9][DD];
    for (int t = threadIdx.x; t < 9 * DD; t += 256) {
        int r = t / DD, d = t % DD;
        int n = (n0 + r) & (NN - 1);
        xs[r][d] = x[((size_t)b * NN + n) * DD + d];
    }
    __syncthreads();

    int c = threadIdx.x;
    unsigned long long accPi[4], accPj[4];   // row pairs (2p, 2p+1)
#pragma unroll
    for (int p = 0; p < 4; p++) { accPi[p] = 0ull; accPj[p] = 0ull; }

#pragma unroll 4
    for (int d = 0; d < DD; d++) {
        float wa = W1[(0 * DD + d) * KK + c];
        float wb = W1[(1 * DD + d) * KK + c];
        float wc = W1[(2 * DD + d) * KK + c];
        float wd = W1[(3 * DD + d) * KK + c];
        unsigned long long wa2 = pack2(wa, wa);
        unsigned long long wb2 = pack2(wb, wb);
        unsigned long long wc2 = pack2(wc, wc);
        unsigned long long wd2 = pack2(wd, wd);
#pragma unroll
        for (int p = 0; p < 4; p++) {
            unsigned long long xv  = pack2(xs[2 * p][d],     xs[2 * p + 1][d]);
            unsigned long long xnv = pack2(xs[2 * p + 1][d], xs[2 * p + 2][d]);
            accPi[p] = fma2(xv,  wa2, accPi[p]);
            accPi[p] = fma2(xnv, wb2, accPi[p]);
            accPj[p] = fma2(xv,  wc2, accPj[p]);
            accPj[p] = fma2(xnv, wd2, accPj[p]);
        }
    }
    float b1c = b1[c];
#pragma unroll
    for (int p = 0; p < 4; p++) {
        float v0, v1, w0, w1;
        unpack2(accPi[p], v0, v1);
        unpack2(accPj[p], w0, w1);
        size_t off0 = ((size_t)b * NN + n0 + 2 * p) * KK + c;
        g_Pih[off0]      = __float2half_rn(v0 + b1c);
        g_Pih[off0 + KK] = __float2half_rn(v1 + b1c);
        g_Pjh[off0]      = __float2half_rn(w0);
        g_Pjh[off0 + KK] = __float2half_rn(w1);
    }
}

// ---------------------------------------------------------------------------
// W2 prep (transpose [k][c] fp32 -> [c][k] half) + fused tour output
// ---------------------------------------------------------------------------
__global__ void w2prep_kernel(const float* __restrict__ W2,
                              float* __restrict__ tourOut, int doTour) {
    int idx = blockIdx.x * 256 + threadIdx.x;  // k*128 + c
    int k = idx >> 7, c = idx & 127;
    g_W2h[c * KK + k] = __float2half_rn(W2[idx]);
    if (doTour && idx < BB * NN) tourOut[idx] = (float)(idx & (NN - 1));
}

// ---------------------------------------------------------------------------
// Pair kernel: CTA = (b, {i0,i0+1}, j-tile of 128), fp16 m16n8k16.
// 512 thr = 16 warps = 8(wy: j 16-range) x 2(wx: c 64-range).
// Each warp handles BOTH i's on ONE 16-row j block -> whole-warp mask skip.
// ---------------------------------------------------------------------------
#define BROW 264                       // half stride: 256+8 (conflict-free)

// byte offsets in dynamic smem
#define OFF_BH   0                     // 128*264*2 = 67584
#define OFF_PJ   67584                 // 128*264*2 = 67584
#define OFF_PI   135168                // 512*2     = 1024
#define OFF_B2   136192                // 512
#define OFF_W3   136704                // 512
#define OFF_RED  137216                // 2*128*2*4 = 2048
#define SMEM_BYTES 139264

__global__ __launch_bounds__(512, 1) void pair_kernel(const float* __restrict__ b2g,
                                                      const float* __restrict__ w3g,
                                                      const float* __restrict__ b3g,
                                                      float* __restrict__ outm) {
    extern __shared__ char smem[];
    __half* Bh  = (__half*)(smem + OFF_BH);
    __half* Pjs = (__half*)(smem + OFF_PJ);
    __half* Pis = (__half*)(smem + OFF_PI);
    float*  b2s = (float*)(smem + OFF_B2);
    float*  w3s = (float*)(smem + OFF_W3);
    float*  red = (float*)(smem + OFF_RED);

    int tid  = threadIdx.x;
    int lane = tid & 31, wid = tid >> 5;
    int wx = wid & 1;                  // c 64-range
    int wy = wid >> 1;                 // j 16-range (0..7)
    int g  = lane >> 2, tg = lane & 3;

    int bid = blockIdx.x;
    int jt = bid & 1;
    int ig = (bid >> 1) & 127;
    int b  = bid >> 8;
    int j0 = jt << 7, i0 = ig << 1;
    if (i0 > j0 + 125) return;         // fully masked tile (output zeroed by memset)

    int jb = j0 + wy * 16;             // this warp's j block base
    bool okA = (jb + 15) >= i0 + 2;    // block valid for i0   (okB implies okA)
    bool okB = (jb + 15) >= i0 + 3;    // block valid for i0+1

    // Prologue: W2 image, Pj j-tile, Pi rows, b2, W3
    {
        const uint4* wsrc = (const uint4*)g_W2h;
#pragma unroll
        for (int q = tid; q < 4096; q += 512) {
            int cc = q >> 5, qq = q & 31;
            *(uint4*)&Bh[cc * BROW + qq * 8] = wsrc[cc * 32 + qq];
        }
        const uint4* psrc = (const uint4*)&g_Pjh[(size_t)(b * NN + j0) * KK];
#pragma unroll
        for (int q = tid; q < 4096; q += 512) {
            int jj = q >> 5, qq = q & 31;
            *(uint4*)&Pjs[jj * BROW + qq * 8] = psrc[jj * 32 + qq];
        }
        const __half* pisrc = &g_Pih[(size_t)(b * NN + i0) * KK];
        Pis[tid] = pisrc[tid];          // 512 halves = both i rows
        if (tid < 128) { b2s[tid] = b2g[tid]; w3s[tid] = w3g[tid]; }
    }
    __syncthreads();   // the only barrier before the epilogue

    float acc[2][8][4];
#pragma unroll
    for (int i = 0; i < 2; i++)
#pragma unroll
        for (int n = 0; n < 8; n++)
#pragma unroll
            for (int q = 0; q < 4; q++) acc[i][n][q] = 0.f;

    if (okA) {
        // ldmatrix lane addresses (bytes)
        uint32_t BhAddr = (uint32_t)__cvta_generic_to_shared(Bh);
        uint32_t PjAddr = (uint32_t)__cvta_generic_to_shared(Pjs);
        int rowL = lane & 15, kL = (lane >> 4) * 8;
        uint32_t bAddr[4];
#pragma unroll
        for (int t = 0; t < 4; t++)
            bAddr[t] = (uint32_t)((wx * 64 + t * 16 + rowL) * BROW + kL) * 2 + BhAddr;
        uint32_t pjAddr = (uint32_t)((wy * 16 + rowL) * BROW + kL) * 2 + PjAddr;

        const __half2 zero2 = __float2half2_rn(0.f);
        const __half* Pi0 = &Pis[0];
        const __half* Pi1 = &Pis[256];

#pragma unroll 4
        for (int c = 0; c < 16; c++) {
            int k0 = c << 4;

            // All loads up front, fully independent
            uint32_t bq[4][4];
#pragma unroll
            for (int t = 0; t < 4; t++) ldx4(bq[t], bAddr[t] + (uint32_t)k0 * 2);
            uint32_t pq[4];
            ldx4(pq, pjAddr + (uint32_t)k0 * 2);
            __half2 pil0 = *(const __half2*)&Pi0[k0 + 2 * tg];
            __half2 pih0 = *(const __half2*)&Pi0[k0 + 2 * tg + 8];
            __half2 pil1 = *(const __half2*)&Pi1[k0 + 2 * tg];
            __half2 pih1 = *(const __half2*)&Pi1[k0 + 2 * tg + 8];

            // i = i0
            {
                uint32_t a0 = h2_as_u32(__hmax2(__hadd2(u32_as_h2(pq[0]), pil0), zero2));
                uint32_t a1 = h2_as_u32(__hmax2(__hadd2(u32_as_h2(pq[1]), pil0), zero2));
                uint32_t a2 = h2_as_u32(__hmax2(__hadd2(u32_as_h2(pq[2]), pih0), zero2));
                uint32_t a3 = h2_as_u32(__hmax2(__hadd2(u32_as_h2(pq[3]), pih0), zero2));
#pragma unroll
                for (int t = 0; t < 4; t++) {
                    mma_f16(acc[0][2 * t],     a0, a1, a2, a3, bq[t][0], bq[t][2]);
                    mma_f16(acc[0][2 * t + 1], a0, a1, a2, a3, bq[t][1], bq[t][3]);
                }
            }
            // i = i0 + 1
            if (okB) {
                uint32_t a0 = h2_as_u32(__hmax2(__hadd2(u32_as_h2(pq[0]), pil1), zero2));
                uint32_t a1 = h2_as_u32(__hmax2(__hadd2(u32_as_h2(pq[1]), pil1), zero2));
                uint32_t a2 = h2_as_u32(__hmax2(__hadd2(u32_as_h2(pq[2]), pih1), zero2));
                uint32_t a3 = h2_as_u32(__hmax2(__hadd2(u32_as_h2(pq[3]), pih1), zero2));
#pragma unroll
                for (int t = 0; t < 4; t++) {
                    mma_f16(acc[1][2 * t],     a0, a1, a2, a3, bq[t][0], bq[t][2]);
                    mma_f16(acc[1][2 * t + 1], a0, a1, a2, a3, bq[t][1], bq[t][3]);
                }
            }
        }
    }

    // Epilogue: relu(C+b2).W3 partial dots, shfl reduce over tg, smem over wx
    float b3v = b3g[0];
#pragma unroll
    for (int i = 0; i < 2; i++) {
        float s0 = 0.f, s1 = 0.f;
#pragma unroll
        for (int n = 0; n < 8; n++) {
            int c0 = wx * 64 + n * 8 + tg * 2;
            float bA  = b2s[c0],     wA  = w3s[c0];
            float bBv = b2s[c0 + 1], wBv = w3s[c0 + 1];
            s0 += fmaxf(acc[i][n][0] + bA, 0.f) * wA
                + fmaxf(acc[i][n][1] + bBv, 0.f) * wBv;
            s1 += fmaxf(acc[i][n][2] + bA, 0.f) * wA
                + fmaxf(acc[i][n][3] + bBv, 0.f) * wBv;
        }
        s0 += __shfl_xor_sync(0xffffffffu, s0, 1);
        s0 += __shfl_xor_sync(0xffffffffu, s0, 2);
        s1 += __shfl_xor_sync(0xffffffffu, s1, 1);
        s1 += __shfl_xor_sync(0xffffffffu, s1, 2);
        if (tg == 0) {
            int r0 = wy * 16 + g;
            red[(i * 128 + r0) * 2 + wx]     = s0;
            red[(i * 128 + r0 + 8) * 2 + wx] = s1;
        }
    }
    __syncthreads();

    if (tid < 256) {
        int i  = tid >> 7;
        int jj = tid & 127;
        const float* rp = &red[(i * 128 + jj) * 2];
        float sum = rp[0] + rp[1] + b3v;
        int iG = i0 + i, j = j0 + jj;
        bool valid = (j >= iG + 2) && ((j - iG) != (NN - 1));
        outm[((size_t)(b * NN + iG)) * NN + j] = valid ? tanhf(sum) : 0.f;
    }
}

// ---------------------------------------------------------------------------
// Launcher
// ---------------------------------------------------------------------------
extern "C" void kernel_launch(void* const* d_in, const int* in_sizes, int n_in,
                              void* d_out, int out_size) {
    const float* x  = (const float*)d_in[0];
    const float* W1 = (const float*)d_in[1];
    const float* b1 = (const float*)d_in[2];
    const float* W2 = (const float*)d_in[3];
    const float* b2 = (const float*)d_in[4];
    const float* W3 = (const float*)d_in[5];
    const float* b3 = (const float*)d_in[6];
    float* out = (float*)d_out;

    const int MAT  = BB * NN * NN;   // 524288
    const int TOUR = BB * NN;        // 2048

    size_t matOff = 0;
    bool hasTour = false;
    if (out_size >= MAT + TOUR) { hasTour = true; matOff = (size_t)out_size - MAT; }

    cudaFuncSetAttribute(pair_kernel, cudaFuncAttributeMaxDynamicSharedMemorySize,
                         SMEM_BYTES);

    cudaMemsetAsync(d_out, 0, (size_t)out_size * sizeof(float), 0);

    proj_kernel<<<256, 256>>>(x, W1, b1);
    w2prep_kernel<<<128, 256>>>(W2, out, hasTour ? 1 : 0);
    pair_kernel<<<BB * 128 * 2, 512, SMEM_BYTES>>>(b2, W3, b3, out + matOff);
}